// round 2
// baseline (speedup 1.0000x reference)
#include <cuda_runtime.h>

#define BATCH 32

__device__ float g_b0[32u * 128 * 128 * 128];
__device__ float g_b1[32u * 256 * 64 * 64];
__device__ float g_b2[32u * 512 * 32 * 32];
__device__ float g_b3[32u * 32 * 64 * 64];
__device__ float g_ze[32u * 64 * 32 * 32];
__device__ float g_zq[32u * 64 * 32 * 32];
__device__ float g_loss[1];

// ---------------- conv k4 s2 p1 : tile 128co x 2oh x 32ow, 256 thr ----------
__global__ void __launch_bounds__(256) conv4s2_kernel(
    const float* __restrict__ in, const float* __restrict__ w,
    const float* __restrict__ bias, float* __restrict__ out,
    int Ci, int Co, int Hi, int Wi, int Ho, int Wo, int relu)
{
    __shared__ float w_s[2][16][128];
    __shared__ float x_s[2][6][66];
    const int tid = threadIdx.x;
    const int wx = tid & 7, cy = tid >> 3;
    const int w0 = blockIdx.x * 32, oh0 = blockIdx.y * 2;
    const int cot = Co >> 7;
    const int b = blockIdx.z / cot, c0 = (blockIdx.z % cot) << 7;
    const int ihb = 4 * (int)blockIdx.y - 1, iwb = 2 * w0 - 1;

    float acc[2][4][4];
#pragma unroll
    for (int r = 0; r < 2; r++)
#pragma unroll
        for (int i = 0; i < 4; i++)
#pragma unroll
            for (int j = 0; j < 4; j++) acc[r][i][j] = 0.f;

    for (int ci0 = 0; ci0 < Ci; ci0 += 2) {
        const int cik = min(2, Ci - ci0);
        for (int idx = tid; idx < cik * 6 * 66; idx += 256) {
            int lc = idx % 66, t = idx / 66, lr = t % 6, ci = t / 6;
            int ih = ihb + lr, iw = iwb + lc;
            float v = 0.f;
            if ((unsigned)ih < (unsigned)Hi && (unsigned)iw < (unsigned)Wi)
                v = in[((size_t)(b * Ci + ci0 + ci) * Hi + ih) * Wi + iw];
            x_s[ci][lr][lc] = v;
        }
        for (int idx = tid; idx < cik * 16 * 128; idx += 256) {
            int t = idx & 15, co = (idx >> 4) & 127, ci = idx >> 11;
            w_s[ci][t][co] = w[((size_t)(c0 + co) * Ci + ci0 + ci) * 16 + t];
        }
        __syncthreads();
        for (int ci = 0; ci < cik; ci++) {
#pragma unroll
            for (int kh = 0; kh < 4; kh++)
#pragma unroll
                for (int kw = 0; kw < 4; kw++) {
                    const float4 wv = *(const float4*)&w_s[ci][(kh << 2) + kw][cy << 2];
                    const float wvv[4] = {wv.x, wv.y, wv.z, wv.w};
#pragma unroll
                    for (int r = 0; r < 2; r++) {
                        const float* xr = &x_s[ci][2 * r + kh][(wx << 3) + kw];
                        const float xv[4] = {xr[0], xr[2], xr[4], xr[6]};
#pragma unroll
                        for (int i = 0; i < 4; i++)
#pragma unroll
                            for (int j = 0; j < 4; j++)
                                acc[r][i][j] = fmaf(wvv[i], xv[j], acc[r][i][j]);
                    }
                }
        }
        __syncthreads();
    }
#pragma unroll
    for (int i = 0; i < 4; i++) {
        const int co = c0 + (cy << 2) + i;
        const float bv = bias ? bias[co] : 0.f;
#pragma unroll
        for (int r = 0; r < 2; r++) {
            float4 o = {acc[r][i][0] + bv, acc[r][i][1] + bv,
                        acc[r][i][2] + bv, acc[r][i][3] + bv};
            if (relu) {
                o.x = fmaxf(o.x, 0.f); o.y = fmaxf(o.y, 0.f);
                o.z = fmaxf(o.z, 0.f); o.w = fmaxf(o.w, 0.f);
            }
            *(float4*)&out[((size_t)(b * Co + co) * Ho + oh0 + r) * Wo + w0 + (wx << 2)] = o;
        }
    }
}

// ---------------- 3x3 conv pad1, Co=32, fused input relu --------------------
__global__ void __launch_bounds__(256) conv3x3_kernel(
    const float* __restrict__ in, const float* __restrict__ w,
    float* __restrict__ out, int Ci, int HW)
{
    __shared__ float w_s[4][9][32];
    __shared__ float x_s[4][10][18];
    const int tid = threadIdx.x;
    const int s = tid & 31, g = tid >> 5;
    const int r = s >> 2, cb = (s & 3) << 2;
    const int ow0 = blockIdx.x * 16, oh0 = blockIdx.y * 8, b = blockIdx.z;

    float acc[4][4];
#pragma unroll
    for (int i = 0; i < 4; i++)
#pragma unroll
        for (int j = 0; j < 4; j++) acc[i][j] = 0.f;

    for (int ci0 = 0; ci0 < Ci; ci0 += 4) {
        for (int idx = tid; idx < 720; idx += 256) {
            int lc = idx % 18, t = idx / 18, lr = t % 10, ci = t / 10;
            int ih = oh0 - 1 + lr, iw = ow0 - 1 + lc;
            float v = 0.f;
            if ((unsigned)ih < (unsigned)HW && (unsigned)iw < (unsigned)HW)
                v = in[((size_t)(b * Ci + ci0 + ci) * HW + ih) * HW + iw];
            x_s[ci][lr][lc] = fmaxf(v, 0.f);
        }
        for (int idx = tid; idx < 1152; idx += 256) {
            int t = idx % 9, q = idx / 9, ci = q & 3, co = q >> 2;
            w_s[ci][t][co] = w[((size_t)co * Ci + ci0 + ci) * 9 + t];
        }
        __syncthreads();
#pragma unroll
        for (int ci = 0; ci < 4; ci++)
#pragma unroll
            for (int kh = 0; kh < 3; kh++)
#pragma unroll
                for (int kw = 0; kw < 3; kw++) {
                    const float4 wv = *(const float4*)&w_s[ci][kh * 3 + kw][g << 2];
                    const float wvv[4] = {wv.x, wv.y, wv.z, wv.w};
                    const float* xr = &x_s[ci][r + kh][cb + kw];
                    const float xv[4] = {xr[0], xr[1], xr[2], xr[3]};
#pragma unroll
                    for (int i = 0; i < 4; i++)
#pragma unroll
                        for (int j = 0; j < 4; j++)
                            acc[i][j] = fmaf(wvv[i], xv[j], acc[i][j]);
                }
        __syncthreads();
    }
#pragma unroll
    for (int i = 0; i < 4; i++) {
        float4 o = {acc[i][0], acc[i][1], acc[i][2], acc[i][3]};
        *(float4*)&out[(((size_t)b * 32 + (g << 2) + i) * HW + oh0 + r) * HW + ow0 + cb] = o;
    }
}

// ---------------- 1x1 conv GEMM: 64co x 64px tile ---------------------------
__global__ void __launch_bounds__(256) conv1x1_kernel(
    const float* __restrict__ in, const float* __restrict__ w,
    const float* __restrict__ bias, float* __restrict__ out,
    int Ci, int Co, int P, int relu_in, int add_res)
{
    __shared__ float w_s[16][64];
    __shared__ float x_s[16][64];
    const int tid = threadIdx.x;
    const int tx = tid & 15, ty = tid >> 4;
    const int p0 = blockIdx.x * 64, c0 = blockIdx.y * 64, b = blockIdx.z;

    float acc[4][4];
#pragma unroll
    for (int i = 0; i < 4; i++)
#pragma unroll
        for (int j = 0; j < 4; j++) acc[i][j] = 0.f;

    for (int ci0 = 0; ci0 < Ci; ci0 += 16) {
        for (int idx = tid; idx < 1024; idx += 256) {
            int p = idx & 63, ci = idx >> 6;
            float v = in[(size_t)(b * Ci + ci0 + ci) * P + p0 + p];
            x_s[ci][p] = relu_in ? fmaxf(v, 0.f) : v;
        }
        for (int idx = tid; idx < 1024; idx += 256) {
            int ci = idx & 15, co = idx >> 4;
            w_s[ci][co] = w[(size_t)(c0 + co) * Ci + ci0 + ci];
        }
        __syncthreads();
#pragma unroll
        for (int ci = 0; ci < 16; ci++) {
            const float4 wv = *(const float4*)&w_s[ci][ty << 2];
            const float4 xv = *(const float4*)&x_s[ci][tx << 2];
            const float wvv[4] = {wv.x, wv.y, wv.z, wv.w};
            const float xvv[4] = {xv.x, xv.y, xv.z, xv.w};
#pragma unroll
            for (int i = 0; i < 4; i++)
#pragma unroll
                for (int j = 0; j < 4; j++)
                    acc[i][j] = fmaf(wvv[i], xvv[j], acc[i][j]);
        }
        __syncthreads();
    }
#pragma unroll
    for (int i = 0; i < 4; i++) {
        const int co = c0 + (ty << 2) + i;
        const float bv = bias ? bias[co] : 0.f;
        const size_t base = (size_t)(b * Co + co) * P + p0 + (tx << 2);
        float4 o = {acc[i][0] + bv, acc[i][1] + bv, acc[i][2] + bv, acc[i][3] + bv};
        if (add_res) {
            float4 rr = *(const float4*)&out[base];
            o.x += rr.x; o.y += rr.y; o.z += rr.z; o.w += rr.w;
        }
        *(float4*)&out[base] = o;
    }
}

// ---------------- VQ: chunked codebook, query in regs -----------------------
__global__ void __launch_bounds__(256) vq_kernel(
    const float* __restrict__ ze, const float* __restrict__ emb,
    float* __restrict__ zq, float* __restrict__ loss)
{
    __shared__ float e_s[128 * 64];
    __shared__ float n_s[128];
    const int tid = threadIdx.x;
    const int n = blockIdx.x * 256 + tid;
    const int b = n >> 10, hw = n & 1023;

    float xr[64];
#pragma unroll
    for (int d = 0; d < 64; d++)
        xr[d] = ze[((size_t)(b * 64 + d) << 10) + hw];

    float best = 3.4e38f;
    int bi = 0;
    for (int kb = 0; kb < 4; kb++) {
        __syncthreads();
        for (int i = tid; i < 128 * 64; i += 256) e_s[i] = emb[kb * 128 * 64 + i];
        __syncthreads();
        if (tid < 128) {
            float s = 0.f;
#pragma unroll 8
            for (int d = 0; d < 64; d++) { float v = e_s[tid * 64 + d]; s = fmaf(v, v, s); }
            n_s[tid] = s;
        }
        __syncthreads();
        for (int k = 0; k < 128; k++) {
            const float4* e4 = (const float4*)(e_s + k * 64);
            float dot = 0.f;
#pragma unroll
            for (int d4 = 0; d4 < 16; d4++) {
                float4 e = e4[d4];
                dot = fmaf(e.x, xr[d4 * 4 + 0], dot);
                dot = fmaf(e.y, xr[d4 * 4 + 1], dot);
                dot = fmaf(e.z, xr[d4 * 4 + 2], dot);
                dot = fmaf(e.w, xr[d4 * 4 + 3], dot);
            }
            float dist = n_s[k] - 2.f * dot;
            if (dist < best) { best = dist; bi = kb * 128 + k; }
        }
    }

    float ls = 0.f;
#pragma unroll
    for (int d = 0; d < 64; d++) {
        float e = emb[bi * 64 + d];
        zq[((size_t)(b * 64 + d) << 10) + hw] = e;
        float df = e - xr[d];
        ls = fmaf(df, df, ls);
    }
#pragma unroll
    for (int o = 16; o > 0; o >>= 1) ls += __shfl_down_sync(0xffffffffu, ls, o);
    if ((tid & 31) == 0) atomicAdd(loss, ls);
}

// ---------------- conv-transpose k4 s2 p1 (parity quads) --------------------
template <int CO_TILE, int CO_PT, int M_TILE, int N_TILE>
__global__ void __launch_bounds__(256) tconv_kernel(
    const float* __restrict__ in, const float* __restrict__ w,
    const float* __restrict__ bias, float* __restrict__ out,
    int Ci, int Co, int Hi, int Wi, int relu_in, int relu_out)
{
    constexpr int NSLOT = (M_TILE * N_TILE) / 4;
    constexpr int CG = CO_TILE / CO_PT;
    static_assert(NSLOT * CG == 256, "map");
    __shared__ float w_s[4][16][CO_TILE];
    __shared__ float x_s[4][M_TILE + 2][N_TILE + 2];

    const int tid = threadIdx.x;
    const int slot = tid % NSLOT, cg = tid / NSLOT;
    const int m_loc = slot / (N_TILE / 4);
    const int nb = (slot % (N_TILE / 4)) * 4;
    const int n0 = blockIdx.x * N_TILE, m0 = blockIdx.y * M_TILE;
    const int cot = (Co + CO_TILE - 1) / CO_TILE;
    const int b = blockIdx.z / cot, c0 = (blockIdx.z % cot) * CO_TILE;
    const int Ho = 2 * Hi, Wo2 = 2 * Wi;

    float acc[CO_PT][4][2][2];
#pragma unroll
    for (int i = 0; i < CO_PT; i++)
#pragma unroll
        for (int q = 0; q < 4; q++)
#pragma unroll
            for (int a = 0; a < 2; a++)
#pragma unroll
                for (int bb = 0; bb < 2; bb++) acc[i][q][a][bb] = 0.f;

    for (int ci0 = 0; ci0 < Ci; ci0 += 4) {
        for (int idx = tid; idx < 4 * (M_TILE + 2) * (N_TILE + 2); idx += 256) {
            int lc = idx % (N_TILE + 2);
            int t = idx / (N_TILE + 2);
            int lr = t % (M_TILE + 2), ci = t / (M_TILE + 2);
            int m = m0 - 1 + lr, nn = n0 - 1 + lc;
            float v = 0.f;
            if ((unsigned)m < (unsigned)Hi && (unsigned)nn < (unsigned)Wi)
                v = in[((size_t)(b * Ci + ci0 + ci) * Hi + m) * Wi + nn];
            if (relu_in) v = fmaxf(v, 0.f);
            x_s[ci][lr][lc] = v;
        }
        for (int idx = tid; idx < 4 * 16 * CO_TILE; idx += 256) {
            int t = idx & 15;
            int co = (idx >> 4) % CO_TILE;
            int ci = idx / (16 * CO_TILE);
            float v = 0.f;
            if (c0 + co < Co) v = w[((size_t)(ci0 + ci) * Co + c0 + co) * 16 + t];
            w_s[ci][t][co] = v;
        }
        __syncthreads();
#pragma unroll
        for (int ci = 0; ci < 4; ci++)
#pragma unroll
            for (int t = 0; t < 16; t++) {
                const int kh = t >> 2, kw = t & 3;
                const int a = 1 - (kh & 1);
                const int dm = (kh == 0) ? 1 : ((kh == 3) ? -1 : 0);
                const int bb = 1 - (kw & 1);
                const int dn = (kw == 0) ? 1 : ((kw == 3) ? -1 : 0);
                float wr[CO_PT];
#pragma unroll
                for (int i = 0; i < CO_PT; i++)
                    wr[i] = w_s[ci][t][cg * CO_PT + i];
                const float* xrow = &x_s[ci][m_loc + dm + 1][nb + dn + 1];
#pragma unroll
                for (int q = 0; q < 4; q++) {
                    const float xv = xrow[q];
#pragma unroll
                    for (int i = 0; i < CO_PT; i++)
                        acc[i][q][a][bb] = fmaf(wr[i], xv, acc[i][q][a][bb]);
                }
            }
        __syncthreads();
    }

    const int m = m0 + m_loc;
#pragma unroll
    for (int i = 0; i < CO_PT; i++) {
        const int co = c0 + cg * CO_PT + i;
        if (co < Co) {
            const float bv = bias[co];
#pragma unroll
            for (int q = 0; q < 4; q++) {
                const int nn = n0 + nb + q;
#pragma unroll
                for (int a = 0; a < 2; a++) {
                    float2 o = {acc[i][q][a][0] + bv, acc[i][q][a][1] + bv};
                    if (relu_out) { o.x = fmaxf(o.x, 0.f); o.y = fmaxf(o.y, 0.f); }
                    *(float2*)&out[((size_t)(b * Co + co) * Ho + 2 * m + a) * Wo2 + 2 * nn] = o;
                }
            }
        }
    }
}

__global__ void zero_loss_kernel(float* loss) { loss[0] = 0.f; }
__global__ void finish_loss_kernel(const float* __restrict__ loss, float* __restrict__ dst)
{
    dst[0] = 2.f * loss[0] / 2097152.f;
}

// ---------------------------------------------------------------------------
extern "C" void kernel_launch(void* const* d_in, const int* in_sizes, int n_in,
                              void* d_out, int out_size)
{
    (void)in_sizes; (void)n_in;
    const float* x       = (const float*)d_in[0];
    const float* enc_w1  = (const float*)d_in[1];
    const float* enc_b1  = (const float*)d_in[2];
    const float* enc_w2  = (const float*)d_in[3];
    const float* enc_b2  = (const float*)d_in[4];
    const float* enc_w3  = (const float*)d_in[5];
    const float* enc_b3  = (const float*)d_in[6];
    const float* enc_rw3 = (const float*)d_in[7];
    const float* enc_rw1 = (const float*)d_in[8];
    const float* prevq_w = (const float*)d_in[9];
    const float* prevq_b = (const float*)d_in[10];
    const float* emb     = (const float*)d_in[11];
    const float* dec_w1  = (const float*)d_in[12];
    const float* dec_b1  = (const float*)d_in[13];
    const float* dec_rw3 = (const float*)d_in[14];
    const float* dec_rw1 = (const float*)d_in[15];
    const float* dec_w2  = (const float*)d_in[16];
    const float* dec_b2  = (const float*)d_in[17];
    const float* dec_w3  = (const float*)d_in[18];
    const float* dec_b3  = (const float*)d_in[19];
    float* out = (float*)d_out;

    float *b0, *b1, *b2, *b3, *ze, *zq, *loss;
    cudaGetSymbolAddress((void**)&b0, g_b0);
    cudaGetSymbolAddress((void**)&b1, g_b1);
    cudaGetSymbolAddress((void**)&b2, g_b2);
    cudaGetSymbolAddress((void**)&b3, g_b3);
    cudaGetSymbolAddress((void**)&ze, g_ze);
    cudaGetSymbolAddress((void**)&zq, g_zq);
    cudaGetSymbolAddress((void**)&loss, g_loss);

    // ---- encoder ----
    conv4s2_kernel<<<dim3(4, 64, 32), 256>>>(x, enc_w1, enc_b1, b0, 3, 128, 256, 256, 128, 128, 1);
    conv4s2_kernel<<<dim3(2, 32, 64), 256>>>(b0, enc_w2, enc_b2, b1, 128, 256, 128, 128, 64, 64, 1);
    conv4s2_kernel<<<dim3(1, 16, 128), 256>>>(b1, enc_w3, enc_b3, b2, 256, 512, 64, 64, 32, 32, 0);
    for (int l = 0; l < 2; l++) {
        conv3x3_kernel<<<dim3(2, 4, 32), 256>>>(b2, enc_rw3, b3, 512, 32);
        conv1x1_kernel<<<dim3(16, 8, 32), 256>>>(b3, enc_rw1, nullptr, b2, 32, 512, 1024, 1, 1);
    }
    conv1x1_kernel<<<dim3(16, 1, 32), 256>>>(b2, prevq_w, prevq_b, ze, 512, 64, 1024, 1, 0);

    // ---- VQ ----
    zero_loss_kernel<<<1, 1>>>(loss);
    vq_kernel<<<128, 256>>>(ze, emb, zq, loss);
    finish_loss_kernel<<<1, 1>>>(loss, out + (out_size - 1));

    // ---- decoder ----
    tconv_kernel<64, 4, 8, 8><<<dim3(4, 4, 128), 256>>>(zq, dec_w1, dec_b1, b1, 64, 256, 32, 32, 0, 0);
    for (int l = 0; l < 2; l++) {
        conv3x3_kernel<<<dim3(4, 8, 32), 256>>>(b1, dec_rw3, b3, 256, 64);
        conv1x1_kernel<<<dim3(64, 4, 32), 256>>>(b3, dec_rw1, nullptr, b1, 32, 256, 4096, 1, 1);
    }
    tconv_kernel<64, 4, 8, 8><<<dim3(8, 8, 64), 256>>>(b1, dec_w2, dec_b2, b0, 256, 128, 64, 64, 1, 1);
    tconv_kernel<4, 1, 16, 16><<<dim3(8, 8, 32), 256>>>(b0, dec_w3, dec_b3, out, 128, 3, 128, 128, 0, 0);
}